// round 5
// baseline (speedup 1.0000x reference)
#include <cuda_runtime.h>
#include <cooperative_groups.h>
#include <cstdint>
#include <math.h>

namespace cg = cooperative_groups;

#define KNN 20
#define MAXN 65536
#define FPS_CTAS 8
#define FPS_THREADS 256
#define FPS_TOTAL (FPS_CTAS * FPS_THREADS)

__device__ float g_xs[MAXN];
__device__ float g_ys[MAXN];
__device__ float g_zs[MAXN];
__device__ int   g_anchors[8192];
__device__ double g_acc;

__device__ __forceinline__ float dev_inf() { return __int_as_float(0x7f800000); }
__device__ __forceinline__ float dev_ninf() { return __int_as_float(0xff800000); }

// ---------------------------------------------------------------------------
// Prep: AoS -> SoA transpose of pos, zero the loss accumulator.
// ---------------------------------------------------------------------------
__global__ void prep_kernel(const float* __restrict__ pos, int N) {
    int i = blockIdx.x * blockDim.x + threadIdx.x;
    if (i == 0) g_acc = 0.0;
    int stride = gridDim.x * blockDim.x;
    for (int j = i; j < N; j += stride) {
        g_xs[j] = pos[3 * j + 0];
        g_ys[j] = pos[3 * j + 1];
        g_zs[j] = pos[3 * j + 2];
    }
}

// ---------------------------------------------------------------------------
// FPS: 8-CTA cluster, points + min-dist fully register-resident.
// Distance arithmetic: fp32, NO fma contraction, reduce order (dx2+dy2)+dz2
// to match XLA's elementwise square + axis reduce. Tie-break: smallest index.
// ---------------------------------------------------------------------------
template <int P>
__global__ void __cluster_dims__(FPS_CTAS, 1, 1) __launch_bounds__(FPS_THREADS, 1)
fps_kernel(int N, int n_anchors) {
    cg::cluster_group cluster = cg::this_cluster();
    unsigned rank = cluster.block_rank();
    int tid = threadIdx.x;
    int g = (int)rank * FPS_THREADS + tid;

    float px[P], py[P], pz[P], md[P];
#pragma unroll
    for (int s = 0; s < P; s++) {
        int i = g + s * FPS_TOTAL;
        bool v = i < N;
        px[s] = v ? g_xs[i] : 0.f;
        py[s] = v ? g_ys[i] : 0.f;
        pz[s] = v ? g_zs[i] : 0.f;
        md[s] = v ? dev_inf() : dev_ninf();
    }

    __shared__ float wd_s[FPS_THREADS / 32];
    __shared__ int   wi_s[FPS_THREADS / 32];
    __shared__ float cd_s[FPS_CTAS];   // candidates, used on rank 0 only
    __shared__ int   ci_s[FPS_CTAS];
    __shared__ int   bcast;

    // first anchor is point 0; first query is pos[0]
    float qx = g_xs[0], qy = g_ys[0], qz = g_zs[0];
    if (rank == 0 && tid == 0) g_anchors[0] = 0;

    for (int it = 1; it < n_anchors; ++it) {
        float bd = dev_ninf();
        int   bi = 0x7fffffff;
#pragma unroll
        for (int s = 0; s < P; s++) {
            float dx = __fsub_rn(px[s], qx);
            float dy = __fsub_rn(py[s], qy);
            float dz = __fsub_rn(pz[s], qz);
            float d  = __fadd_rn(__fadd_rn(__fmul_rn(dx, dx), __fmul_rn(dy, dy)),
                                 __fmul_rn(dz, dz));
            float m = fminf(md[s], d);
            md[s] = m;
            // strict > with ascending s keeps smallest index on ties
            if (m > bd) { bd = m; bi = g + s * FPS_TOTAL; }
        }
        // warp reduce: max d, tie -> min idx
#pragma unroll
        for (int off = 16; off > 0; off >>= 1) {
            float od = __shfl_down_sync(0xffffffffu, bd, off);
            int   oi = __shfl_down_sync(0xffffffffu, bi, off);
            if (od > bd || (od == bd && oi < bi)) { bd = od; bi = oi; }
        }
        if ((tid & 31) == 0) { wd_s[tid >> 5] = bd; wi_s[tid >> 5] = bi; }
        __syncthreads();
        if (tid == 0) {
#pragma unroll
            for (int w = 1; w < FPS_THREADS / 32; w++) {
                float od = wd_s[w]; int oi = wi_s[w];
                if (od > bd || (od == bd && oi < bi)) { bd = od; bi = oi; }
            }
            float* rd = cluster.map_shared_rank(cd_s, 0);
            int*   ri = cluster.map_shared_rank(ci_s, 0);
            rd[rank] = bd;
            ri[rank] = bi;
        }
        cluster.sync();
        if (rank == 0 && tid == 0) {
            float fd = cd_s[0]; int fi = ci_s[0];
#pragma unroll
            for (int r = 1; r < FPS_CTAS; r++) {
                float od = cd_s[r]; int oi = ci_s[r];
                if (od > fd || (od == fd && oi < fi)) { fd = od; fi = oi; }
            }
            g_anchors[it] = fi;
#pragma unroll
            for (int r = 0; r < FPS_CTAS; r++) {
                *cluster.map_shared_rank(&bcast, r) = fi;
            }
        }
        cluster.sync();
        int wi = bcast;
        qx = g_xs[wi]; qy = g_ys[wi]; qz = g_zs[wi];
    }
}

// ---------------------------------------------------------------------------
// kNN (block per anchor) + 3x3 PCA + per-anchor loss term.
// Candidate key packs (d_bits<<32 | idx): for d >= 0, u64 ascending order ==
// (d ascending, idx ascending) == jax.lax.top_k tie-break.
// ---------------------------------------------------------------------------
__global__ void __launch_bounds__(128)
knn_kernel(const float* __restrict__ vec_pred, int N, int n_anchors) {
    const int b = blockIdx.x;
    const int tid = threadIdx.x;

    const int ai = g_anchors[b];
    const float ax = g_xs[ai], ay = g_ys[ai], az = g_zs[ai];

    const unsigned long long KMAX = 0xffffffffffffffffull;
    unsigned long long ck[KNN];
#pragma unroll
    for (int k = 0; k < KNN; k++) ck[k] = KMAX;
    unsigned long long wk = KMAX;  // current worst (max) key
    int wp = 0;

    for (int i = tid; i < N; i += 128) {
        float dx = g_xs[i] - ax;
        float dy = g_ys[i] - ay;
        float dz = g_zs[i] - az;
        float d = fmaf(dx, dx, fmaf(dy, dy, dz * dz));
        unsigned long long key =
            ((unsigned long long)(unsigned)__float_as_int(d) << 32) | (unsigned)i;
        if (key < wk) {
            ck[wp] = key;
            unsigned long long nw = 0; int np = 0;
#pragma unroll
            for (int k = 0; k < KNN; k++) {
                if (ck[k] > nw) { nw = ck[k]; np = k; }
            }
            wk = nw; wp = np;
        }
    }

    __shared__ unsigned long long swk[4];
    __shared__ unsigned long long gwin;
    __shared__ int nn[KNN];
    __shared__ float nx[KNN], ny_[KNN], nz[KNN];

    // 20 rounds of block-wide min selection
    for (int r = 0; r < KNN; r++) {
        unsigned long long lb = KMAX; int lp = -1;
#pragma unroll
        for (int k = 0; k < KNN; k++) {
            if (ck[k] < lb) { lb = ck[k]; lp = k; }
        }
        unsigned long long rb = lb;
#pragma unroll
        for (int off = 16; off > 0; off >>= 1) {
            unsigned long long ob = __shfl_down_sync(0xffffffffu, rb, off);
            if (ob < rb) rb = ob;
        }
        if ((tid & 31) == 0) swk[tid >> 5] = rb;
        __syncthreads();
        if (tid == 0) {
            unsigned long long fb = swk[0];
            for (int w = 1; w < 4; w++) if (swk[w] < fb) fb = swk[w];
            gwin = fb;
            nn[r] = (int)(unsigned)(fb & 0xffffffffull);
        }
        __syncthreads();
        if (lp >= 0 && lb == gwin) { ck[lp] = KMAX; }
    }
    __syncthreads();

    if (tid < KNN) {
        int i = nn[tid];
        nx[tid]  = g_xs[i];
        ny_[tid] = g_ys[i];
        nz[tid]  = g_zs[i];
    }
    __syncthreads();

    if (tid == 0) {
        // mean + covariance in double
        double mx = 0, my = 0, mz = 0;
        for (int k = 0; k < KNN; k++) { mx += nx[k]; my += ny_[k]; mz += nz[k]; }
        mx /= KNN; my /= KNN; mz /= KNN;
        double a00 = 0, a01 = 0, a02 = 0, a11 = 0, a12 = 0, a22 = 0;
        for (int k = 0; k < KNN; k++) {
            double cx = (double)nx[k] - mx;
            double cy = (double)ny_[k] - my;
            double cz = (double)nz[k] - mz;
            a00 += cx * cx; a01 += cx * cy; a02 += cx * cz;
            a11 += cy * cy; a12 += cy * cz; a22 += cz * cz;
        }

        // closed-form top eigenvector of symmetric 3x3
        double vx = 1.0, vy = 0.0, vz = 0.0;
        double p1 = a01 * a01 + a02 * a02 + a12 * a12;
        if (p1 < 1e-300) {
            if (a00 >= a11 && a00 >= a22)      { vx = 1; vy = 0; vz = 0; }
            else if (a11 >= a22)               { vx = 0; vy = 1; vz = 0; }
            else                               { vx = 0; vy = 0; vz = 1; }
        } else {
            double q = (a00 + a11 + a22) / 3.0;
            double p2 = (a00 - q) * (a00 - q) + (a11 - q) * (a11 - q) +
                        (a22 - q) * (a22 - q) + 2.0 * p1;
            double p = sqrt(p2 / 6.0);
            double b00 = (a00 - q) / p, b11 = (a11 - q) / p, b22 = (a22 - q) / p;
            double b01 = a01 / p, b02 = a02 / p, b12 = a12 / p;
            double detB = b00 * (b11 * b22 - b12 * b12)
                        - b01 * (b01 * b22 - b12 * b02)
                        + b02 * (b01 * b12 - b11 * b02);
            double rr = detB * 0.5;
            rr = fmin(1.0, fmax(-1.0, rr));
            double phi = acos(rr) / 3.0;
            double lam = q + 2.0 * p * cos(phi);

            double m00 = a00 - lam, m11 = a11 - lam, m22 = a22 - lam;
            // cross products of rows of (C - lam I)
            double c1x = a01 * a12 - a02 * m11;
            double c1y = a02 * a01 - m00 * a12;
            double c1z = m00 * m11 - a01 * a01;
            double c2x = a01 * m22 - a02 * a12;
            double c2y = a02 * a02 - m00 * m22;
            double c2z = m00 * a12 - a01 * a02;
            double c3x = m11 * m22 - a12 * a12;
            double c3y = a12 * a02 - a01 * m22;
            double c3z = a01 * a12 - m11 * a02;
            double n1 = c1x * c1x + c1y * c1y + c1z * c1z;
            double n2 = c2x * c2x + c2y * c2y + c2z * c2z;
            double n3 = c3x * c3x + c3y * c3y + c3z * c3z;
            double bx, by, bz, bn;
            if (n1 >= n2 && n1 >= n3)      { bx = c1x; by = c1y; bz = c1z; bn = n1; }
            else if (n2 >= n3)             { bx = c2x; by = c2y; bz = c2z; bn = n2; }
            else                           { bx = c3x; by = c3y; bz = c3z; bn = n3; }
            if (bn > 1e-300) {
                double inv = rsqrt(bn);
                vx = bx * inv; vy = by * inv; vz = bz * inv;
            }
        }

        // loss term: a = vec_pred[b], b = v (unit)
        double pax = (double)vec_pred[3 * b + 0];
        double pay = (double)vec_pred[3 * b + 1];
        double paz = (double)vec_pred[3 * b + 2];
        double na = sqrt(pax * pax + pay * pay + paz * paz);
        na = fmax(na, 1e-8);
        double nb = sqrt(vx * vx + vy * vy + vz * vz);
        nb = fmax(nb, 1e-8);
        double dotv = pax * vx + pay * vy + paz * vz;
        double c = fabs(dotv) / (na * nb);
        double term = log(c + 1e-6);
        atomicAdd(&g_acc, term);
    }
}

__global__ void finalize_kernel(float* out, int n_anchors) {
    out[0] = (float)(-g_acc / (double)n_anchors);
}

// ---------------------------------------------------------------------------
extern "C" void kernel_launch(void* const* d_in, const int* in_sizes, int n_in,
                              void* d_out, int out_size) {
    const float* vec_pred = (const float*)d_in[0];
    const float* pos      = (const float*)d_in[1];
    int N = in_sizes[1] / 3;
    int n_anchors = (N + 9) / 10;  // ceil(0.1 * N) for these sizes

    prep_kernel<<<64, 256>>>(pos, N);

    int P = (N + FPS_TOTAL - 1) / FPS_TOTAL;
    if (P <= 20) {
        fps_kernel<20><<<FPS_CTAS, FPS_THREADS>>>(N, n_anchors);
    } else {
        fps_kernel<32><<<FPS_CTAS, FPS_THREADS>>>(N, n_anchors);
    }

    knn_kernel<<<n_anchors, 128>>>(vec_pred, N, n_anchors);
    finalize_kernel<<<1, 1>>>((float*)d_out, n_anchors);
}